// round 16
// baseline (speedup 1.0000x reference)
#include <cuda_runtime.h>
#include <cuda_bf16.h>
#include <cuda_fp16.h>
#include <cstdint>

#define NUM_USERS 100000
#define NUM_ITEMS 100000
#define NUM_NODES (NUM_USERS + NUM_ITEMS)
#define EMB_DIM 64
#define NUM_EDGES 4000000
#define BATCH 4096
#define CHUNKS 16   // 16 float4 per node row (fp32 arrays)

// bitmask flags: 200000 bits -> 6250 words, padded to 6256 (uint4 multiple)
#define FB_WORDS 6256
#define FB_U4 (FB_WORDS / 4)

// padded row count for scans: 784 * 256
#define NR 200704
#define NR_U4 (NR / 4)          // uint4 count for unsigned[NR]
#define NBLK 784                // NR / 256

// ---- scratch (device globals: allocation-free) ----
__device__ uint4  g_h1h[NUM_NODES * 8];              // fp16 h1: 64 halves/node = 25.6 MB
__device__ float4 g_h2[NUM_NODES * CHUNKS];          // fp32 h2 (only flagged rows valid)
__device__ uint4  g_embh[NUM_NODES * 8];             // fp16 copy of all_emb, 25.6 MB
__device__ unsigned g_fbA[FB_WORDS];                 // batch-row bitmask (layer2 filter)
__device__ unsigned g_fbB[FB_WORDS];                 // needed-h1-row bitmask (layer1 filter)
__device__ int4 g_l2[NUM_EDGES];                     // packed {row,col,val,0} layer2 edges
__device__ uint2 g_e1[NUM_EDGES];                    // CSR payload {col, val} layer1 edges
__device__ unsigned g_cnt[NR];                       // per-row kept-edge counts
__device__ unsigned g_cur[NR];                       // per-row scatter cursors
__device__ unsigned g_pfx[NR];                       // in-block exclusive prefix of cnt
__device__ unsigned g_bsum[NBLK];                    // per-block sums
__device__ unsigned g_boff[NBLK];                    // exclusive prefix of block sums
__device__ int g_c2;

__device__ __forceinline__ void red_add_v4_f32(float4* addr, float4 v) {
    asm volatile("red.global.add.v4.f32 [%0], {%1, %2, %3, %4};"
                 :: "l"(addr), "f"(v.x), "f"(v.y), "f"(v.z), "f"(v.w)
                 : "memory");
}

__device__ __forceinline__ bool test_bit(const unsigned* fb, int n) {
    return (__ldg(fb + (n >> 5)) >> (n & 31)) & 1u;
}

// ---- K_init: zero h1h + bitmasks + cnt/cur + counter, build fp16 emb table ----
#define H1H_WORDS (NUM_NODES * 8)                     // 1.6M uint4
#define CVT_GROUPS (NUM_NODES * EMB_DIM / 8)          // 1.6M (8 floats per thread)
#define CVT_USER_GROUPS (NUM_USERS * EMB_DIM / 8)     // 800K
#define A1 (H1H_WORDS)
#define A2 (A1 + FB_U4)
#define A3 (A2 + FB_U4)
#define A4 (A3 + NR_U4)
#define A5 (A4 + NR_U4)
#define INIT_TOTAL (A5 + CVT_GROUPS)
__global__ void k_init(const float4* __restrict__ user_emb,
                       const float4* __restrict__ item_emb) {
    int i = blockIdx.x * blockDim.x + threadIdx.x;
    if (i == 0) g_c2 = 0;
    if (i < A1) {
        g_h1h[i] = make_uint4(0u, 0u, 0u, 0u);
    } else if (i < A2) {
        ((uint4*)g_fbA)[i - A1] = make_uint4(0u, 0u, 0u, 0u);
    } else if (i < A3) {
        ((uint4*)g_fbB)[i - A2] = make_uint4(0u, 0u, 0u, 0u);
    } else if (i < A4) {
        ((uint4*)g_cnt)[i - A3] = make_uint4(0u, 0u, 0u, 0u);
    } else if (i < A5) {
        ((uint4*)g_cur)[i - A4] = make_uint4(0u, 0u, 0u, 0u);
    } else if (i < INIT_TOTAL) {
        int g = i - A5;
        const float4* src = (g < CVT_USER_GROUPS)
            ? (user_emb + (size_t)g * 2)
            : (item_emb + (size_t)(g - CVT_USER_GROUPS) * 2);
        float4 a = __ldg(src);
        float4 b = __ldg(src + 1);
        __half2 h0 = __floats2half2_rn(a.x, a.y);
        __half2 h1 = __floats2half2_rn(a.z, a.w);
        __half2 h2 = __floats2half2_rn(b.x, b.y);
        __half2 h3 = __floats2half2_rn(b.z, b.w);
        uint4 o;
        o.x = *reinterpret_cast<unsigned*>(&h0);
        o.y = *reinterpret_cast<unsigned*>(&h1);
        o.z = *reinterpret_cast<unsigned*>(&h2);
        o.w = *reinterpret_cast<unsigned*>(&h3);
        g_embh[g] = o;
    }
}

// ---- K_flag: set batch bits (both masks) + zero those h2 rows ----
__global__ void k_flag(const int* __restrict__ user,
                       const int* __restrict__ pos,
                       const int* __restrict__ neg) {
    int t = blockIdx.x * blockDim.x + threadIdx.x;   // 3*BATCH*16 threads
    int g = t >> 4;
    int c = t & 15;
    if (g >= 3 * BATCH) return;
    int node;
    if (g < BATCH)            node = user[g];
    else if (g < 2 * BATCH)   node = NUM_USERS + pos[g - BATCH];
    else                      node = NUM_USERS + neg[g - 2 * BATCH];
    if (c == 0) {
        unsigned bit = 1u << (node & 31);
        atomicOr(&g_fbA[node >> 5], bit);
        atomicOr(&g_fbB[node >> 5], bit);
    }
    g_h2[node * CHUNKS + c] = make_float4(0.f, 0.f, 0.f, 0.f);
}

// ---- K_compactA: layer-2 compaction (keep ~6%) + fbB[col] marking ----
#define COMPACT_THREADS (NUM_EDGES / 4)               // 1,000,000
__global__ void k_compactA(const int* __restrict__ edge_row,
                           const int* __restrict__ edge_col,
                           const float* __restrict__ edge_val) {
    __shared__ int s_cnt;
    __shared__ int s_base;
    __shared__ int s_warp_off[8];

    const int4*   rows4 = (const int4*)edge_row;
    const int4*   cols4 = (const int4*)edge_col;
    const float4* vals4 = (const float4*)edge_val;

    int t = blockIdx.x * blockDim.x + threadIdx.x;
    int lane = threadIdx.x & 31;
    int warp = threadIdx.x >> 5;
    if (threadIdx.x == 0) s_cnt = 0;
    __syncthreads();

    int4 r = make_int4(0, 0, 0, 0), cc = make_int4(0, 0, 0, 0);
    float4 vv = make_float4(0.f, 0.f, 0.f, 0.f);
    bool k0 = false, k1 = false, k2 = false, k3 = false;
    if (t < COMPACT_THREADS) {
        r  = __ldg(rows4 + t);
        k0 = test_bit(g_fbA, r.x);
        k1 = test_bit(g_fbA, r.y);
        k2 = test_bit(g_fbA, r.z);
        k3 = test_bit(g_fbA, r.w);
        if (k0 | k1 | k2 | k3) {
            cc = __ldg(cols4 + t);
            vv = __ldg(vals4 + t);
            if (k0) atomicOr(&g_fbB[cc.x >> 5], 1u << (cc.x & 31));
            if (k1) atomicOr(&g_fbB[cc.y >> 5], 1u << (cc.y & 31));
            if (k2) atomicOr(&g_fbB[cc.z >> 5], 1u << (cc.z & 31));
            if (k3) atomicOr(&g_fbB[cc.w >> 5], 1u << (cc.w & 31));
        }
    }
    int n = (int)k0 + (int)k1 + (int)k2 + (int)k3;
    int pre = n;
    #pragma unroll
    for (int o = 1; o < 32; o <<= 1) {
        int x = __shfl_up_sync(0xFFFFFFFFu, pre, o);
        if (lane >= o) pre += x;
    }
    int excl = pre - n;
    int wtot = __shfl_sync(0xFFFFFFFFu, pre, 31);

    if (lane == 31) s_warp_off[warp] = atomicAdd(&s_cnt, wtot);
    __syncthreads();
    if (threadIdx.x == 0) s_base = atomicAdd(&g_c2, s_cnt);
    __syncthreads();

    int p = s_base + s_warp_off[warp] + excl;
    if (k0) g_l2[p++] = make_int4(r.x, cc.x, __float_as_int(vv.x), 0);
    if (k1) g_l2[p++] = make_int4(r.y, cc.y, __float_as_int(vv.y), 0);
    if (k2) g_l2[p++] = make_int4(r.z, cc.z, __float_as_int(vv.z), 0);
    if (k3) g_l2[p++] = make_int4(r.w, cc.w, __float_as_int(vv.w), 0);
}

// ---- K_histo: count kept layer-1 edges per row ----
__global__ void k_histo(const int* __restrict__ edge_row) {
    int t = blockIdx.x * blockDim.x + threadIdx.x;
    if (t >= COMPACT_THREADS) return;
    int4 r = __ldg((const int4*)edge_row + t);
    if (test_bit(g_fbB, r.x)) atomicAdd(&g_cnt[r.x], 1u);
    if (test_bit(g_fbB, r.y)) atomicAdd(&g_cnt[r.y], 1u);
    if (test_bit(g_fbB, r.z)) atomicAdd(&g_cnt[r.z], 1u);
    if (test_bit(g_fbB, r.w)) atomicAdd(&g_cnt[r.w], 1u);
}

// ---- K_scan1: per-block (256-elem) exclusive scan of g_cnt ----
__global__ void k_scan1(void) {
    int tid = threadIdx.x;
    int lane = tid & 31;
    int warp = tid >> 5;
    int gid = blockIdx.x * 256 + tid;
    unsigned v = g_cnt[gid];
    unsigned x = v;
    #pragma unroll
    for (int o = 1; o < 32; o <<= 1) {
        unsigned u = __shfl_up_sync(0xFFFFFFFFu, x, o);
        if (lane >= o) x += u;
    }
    __shared__ unsigned ws[8];
    if (lane == 31) ws[warp] = x;
    __syncthreads();
    if (tid == 0) {
        unsigned s = 0;
        #pragma unroll
        for (int w = 0; w < 8; w++) { unsigned tmp = ws[w]; ws[w] = s; s += tmp; }
    }
    __syncthreads();
    unsigned excl = x - v + ws[warp];
    g_pfx[gid] = excl;
    if (tid == 255) g_bsum[blockIdx.x] = excl + v;
}

// ---- K_scan2: exclusive scan of NBLK block sums (single block) ----
__global__ void k_scan2(void) {
    int tid = threadIdx.x;          // 1024 threads
    int lane = tid & 31;
    int warp = tid >> 5;
    unsigned v = (tid < NBLK) ? g_bsum[tid] : 0u;
    unsigned x = v;
    #pragma unroll
    for (int o = 1; o < 32; o <<= 1) {
        unsigned u = __shfl_up_sync(0xFFFFFFFFu, x, o);
        if (lane >= o) x += u;
    }
    __shared__ unsigned ws[32];
    if (lane == 31) ws[warp] = x;
    __syncthreads();
    if (tid == 0) {
        unsigned s = 0;
        #pragma unroll
        for (int w = 0; w < 32; w++) { unsigned tmp = ws[w]; ws[w] = s; s += tmp; }
    }
    __syncthreads();
    unsigned excl = x - v + ws[warp];
    if (tid < NBLK) g_boff[tid] = excl;
}

// ---- K_scatter: place kept layer-1 edges into row buckets ----
__global__ void k_scatter(const int* __restrict__ edge_row,
                          const int* __restrict__ edge_col,
                          const float* __restrict__ edge_val) {
    int t = blockIdx.x * blockDim.x + threadIdx.x;
    if (t >= COMPACT_THREADS) return;
    int4 r = __ldg((const int4*)edge_row + t);
    int4 c = __ldg((const int4*)edge_col + t);
    float4 v = __ldg((const float4*)edge_val + t);
    #pragma unroll
    for (int j = 0; j < 4; j++) {
        int row  = (j == 0) ? r.x : (j == 1) ? r.y : (j == 2) ? r.z : r.w;
        int col  = (j == 0) ? c.x : (j == 1) ? c.y : (j == 2) ? c.z : c.w;
        float vv = (j == 0) ? v.x : (j == 1) ? v.y : (j == 2) ? v.z : v.w;
        if (test_bit(g_fbB, row)) {
            unsigned pos = g_pfx[row] + g_boff[row >> 8] + atomicAdd(&g_cur[row], 1u);
            g_e1[pos] = make_uint2((unsigned)col, (unsigned)__float_as_int(vv));
        }
    }
}

// ---- K1: CSR SPMM layer 1: warp per row, fp32 reg accumulation, plain store ----
__global__ void k_spmm1(void) {
    int w = (blockIdx.x * blockDim.x + threadIdx.x) >> 5;   // row id
    int lane = threadIdx.x & 31;
    if (w >= NUM_NODES) return;
    unsigned cnt = g_cnt[w];
    if (cnt == 0) return;
    unsigned base = g_pfx[w] + g_boff[w >> 8];
    int c = lane & 7;        // chunk (16B of the 128B row)
    int sub = lane >> 3;     // edge sub-slot 0..3

    float acc0 = 0.f, acc1 = 0.f, acc2 = 0.f, acc3 = 0.f;
    float acc4 = 0.f, acc5 = 0.f, acc6 = 0.f, acc7 = 0.f;

    for (unsigned j0 = 0; j0 < cnt; j0 += 4) {
        unsigned j = j0 + sub;
        if (j < cnt) {
            uint2 e = __ldg(&g_e1[base + j]);           // broadcast within 8 lanes
            float v = __int_as_float(e.y);
            uint4 u = __ldg(&g_embh[((size_t)e.x << 3) + c]);
            __half2 a = *reinterpret_cast<__half2*>(&u.x);
            __half2 b = *reinterpret_cast<__half2*>(&u.y);
            __half2 d = *reinterpret_cast<__half2*>(&u.z);
            __half2 g = *reinterpret_cast<__half2*>(&u.w);
            float2 fa = __half22float2(a);
            float2 fb = __half22float2(b);
            float2 fd = __half22float2(d);
            float2 fg = __half22float2(g);
            acc0 += v * fa.x; acc1 += v * fa.y;
            acc2 += v * fb.x; acc3 += v * fb.y;
            acc4 += v * fd.x; acc5 += v * fd.y;
            acc6 += v * fg.x; acc7 += v * fg.y;
        }
    }
    // reduce across the 4 edge sub-slots (lane bits 3 and 4)
    #pragma unroll
    for (int m = 8; m <= 16; m <<= 1) {
        acc0 += __shfl_xor_sync(0xFFFFFFFFu, acc0, m);
        acc1 += __shfl_xor_sync(0xFFFFFFFFu, acc1, m);
        acc2 += __shfl_xor_sync(0xFFFFFFFFu, acc2, m);
        acc3 += __shfl_xor_sync(0xFFFFFFFFu, acc3, m);
        acc4 += __shfl_xor_sync(0xFFFFFFFFu, acc4, m);
        acc5 += __shfl_xor_sync(0xFFFFFFFFu, acc5, m);
        acc6 += __shfl_xor_sync(0xFFFFFFFFu, acc6, m);
        acc7 += __shfl_xor_sync(0xFFFFFFFFu, acc7, m);
    }
    if (lane < 8) {
        __half2 h0 = __floats2half2_rn(acc0, acc1);
        __half2 h1 = __floats2half2_rn(acc2, acc3);
        __half2 h2 = __floats2half2_rn(acc4, acc5);
        __half2 h3 = __floats2half2_rn(acc6, acc7);
        uint4 o;
        o.x = *reinterpret_cast<unsigned*>(&h0);
        o.y = *reinterpret_cast<unsigned*>(&h1);
        o.z = *reinterpret_cast<unsigned*>(&h2);
        o.w = *reinterpret_cast<unsigned*>(&h3);
        g_h1h[((size_t)w << 3) + c] = o;
    }
}

// ---- K2: SPMM layer 2: h2[row] += val * h1h[col] (fp16 gather, fp32 red) ----
__global__ void k_spmm2(void) {
    long long total = (long long)g_c2 * CHUNKS;
    long long stride = (long long)gridDim.x * blockDim.x;
    const uint2* h1 = (const uint2*)g_h1h;   // 4 halves per uint2
    for (long long t = (long long)blockIdx.x * blockDim.x + threadIdx.x;
         t < total; t += stride) {
        int idx = (int)(t >> 4);
        int c = (int)(t & 15);
        int4 m = __ldg(&g_l2[idx]);
        float v = __int_as_float(m.z);
        uint2 u = __ldg(&h1[((size_t)m.y << 4) + c]);
        __half2 ha = *reinterpret_cast<__half2*>(&u.x);
        __half2 hb = *reinterpret_cast<__half2*>(&u.y);
        float2 fa = __half22float2(ha);
        float2 fb = __half22float2(hb);
        float4 acc = make_float4(v * fa.x, v * fa.y, v * fb.x, v * fb.y);
        red_add_v4_f32(&g_h2[(size_t)m.x * CHUNKS + c], acc);
    }
}

// ---- K3: gather acc at batch nodes, dot, write scores ----
__global__ void k_score(const int* __restrict__ user,
                        const int* __restrict__ pos,
                        const int* __restrict__ neg,
                        const float2* __restrict__ user_emb2,
                        const float2* __restrict__ item_emb2,
                        float* __restrict__ out) {
    int w = (blockIdx.x * blockDim.x + threadIdx.x) >> 5;
    int lane = threadIdx.x & 31;
    if (w >= BATCH) return;
    int nu = user[w];
    int np = NUM_USERS + pos[w];
    int nn = NUM_USERS + neg[w];

    const unsigned* h1u = (const unsigned*)g_h1h;   // 2 halves per word
    const float2* h2 = (const float2*)g_h2;
    const int L = EMB_DIM / 2;

    unsigned w1u = __ldg(&h1u[(size_t)nu * L + lane]);
    __half2 hu = *reinterpret_cast<__half2*>(&w1u);
    float2 u1 = __half22float2(hu);
    float2 ue = user_emb2[(size_t)nu * L + lane];
    float2 u2 = h2[(size_t)nu * L + lane];
    float ux = ue.x + u1.x + u2.x;
    float uy = ue.y + u1.y + u2.y;

    unsigned w1p = __ldg(&h1u[(size_t)np * L + lane]);
    __half2 hp = *reinterpret_cast<__half2*>(&w1p);
    float2 p1 = __half22float2(hp);
    float2 pe = item_emb2[(size_t)(np - NUM_USERS) * L + lane];
    float2 p2 = h2[(size_t)np * L + lane];
    float px = pe.x + p1.x + p2.x;
    float py = pe.y + p1.y + p2.y;

    unsigned w1n = __ldg(&h1u[(size_t)nn * L + lane]);
    __half2 hn = *reinterpret_cast<__half2*>(&w1n);
    float2 n1 = __half22float2(hn);
    float2 ne = item_emb2[(size_t)(nn - NUM_USERS) * L + lane];
    float2 n2 = h2[(size_t)nn * L + lane];
    float nx = ne.x + n1.x + n2.x;
    float ny = ne.y + n1.y + n2.y;

    float sp = ux * px + uy * py;
    float sn = ux * nx + uy * ny;
    #pragma unroll
    for (int off = 16; off > 0; off >>= 1) {
        sp += __shfl_xor_sync(0xFFFFFFFFu, sp, off);
        sn += __shfl_xor_sync(0xFFFFFFFFu, sn, off);
    }
    if (lane == 0) {
        const float inv9 = 1.0f / 9.0f;
        out[w]         = sp * inv9;
        out[BATCH + w] = sn * inv9;
    }
}

extern "C" void kernel_launch(void* const* d_in, const int* in_sizes, int n_in,
                              void* d_out, int out_size) {
    const int*   user     = (const int*)  d_in[0];
    const int*   pos      = (const int*)  d_in[1];
    const int*   neg      = (const int*)  d_in[2];
    const int*   edge_row = (const int*)  d_in[3];
    const int*   edge_col = (const int*)  d_in[4];
    const float* edge_val = (const float*)d_in[5];
    const float* user_emb = (const float*)d_in[6];
    const float* item_emb = (const float*)d_in[7];
    float* out = (float*)d_out;

    // Init: zero h1h/bitmasks/cnt/cur/counter + build fp16 emb table
    k_init<<<(INIT_TOTAL + 255) / 256, 256>>>((const float4*)user_emb,
                                              (const float4*)item_emb);
    // Batch flag bits + zero needed h2 rows
    {
        int total = 3 * BATCH * CHUNKS;
        k_flag<<<(total + 255) / 256, 256>>>(user, pos, neg);
    }
    // Compact layer-2 edges (bitmask filter, ~6% keep) + mark fbB[col]
    k_compactA<<<(COMPACT_THREADS + 255) / 256, 256>>>(edge_row, edge_col, edge_val);
    // CSR build for layer 1: histogram -> scan -> scatter
    k_histo<<<(COMPACT_THREADS + 255) / 256, 256>>>(edge_row);
    k_scan1<<<NBLK, 256>>>();
    k_scan2<<<1, 1024>>>();
    k_scatter<<<(COMPACT_THREADS + 255) / 256, 256>>>(edge_row, edge_col, edge_val);
    // SPMM layer 1: warp per row, fp32 accumulation, plain stores
    k_spmm1<<<(NUM_NODES * 32 + 255) / 256, 256>>>();
    // SPMM layer 2 over compacted list
    k_spmm2<<<8192, 256>>>();
    // Scores
    {
        int threads = 256;
        int blocks = (BATCH * 32 + threads - 1) / threads;
        k_score<<<blocks, threads>>>(user, pos, neg,
                                     (const float2*)user_emb, (const float2*)item_emb,
                                     out);
    }
}

// round 17
// speedup vs baseline: 1.4267x; 1.4267x over previous
#include <cuda_runtime.h>
#include <cuda_bf16.h>
#include <cuda_fp16.h>
#include <cstdint>

#define NUM_USERS 100000
#define NUM_ITEMS 100000
#define NUM_NODES (NUM_USERS + NUM_ITEMS)
#define EMB_DIM 64
#define NUM_EDGES 4000000
#define BATCH 4096
#define CHUNKS 16

// bitmask flags: 200000 bits -> 6250 words, padded to 6256 (uint4 multiple)
#define FB_WORDS 6256
#define FB_U4 (FB_WORDS / 4)

// ---- scratch (device globals: allocation-free) ----
__device__ uint4  g_h1h[NUM_NODES * 8];              // fp16 h1: 64 halves/node = 25.6 MB
__device__ uint4  g_h2h[NUM_NODES * 8];              // fp16 h2 (only batch rows valid)
__device__ uint4  g_embh[NUM_NODES * 8];             // fp16 copy of all_emb, 25.6 MB
__device__ unsigned g_fbA[FB_WORDS];                 // batch-row bitmask (layer2 filter)
__device__ unsigned g_fbB[FB_WORDS];                 // needed-h1-row bitmask (layer1 filter)
__device__ unsigned long long g_p2[NUM_EDGES];       // packed {row:18,col:18,valh:16} layer2
__device__ unsigned long long g_p1[NUM_EDGES];       // packed {row:18,col:18,valh:16} layer1
__device__ int g_c2;
__device__ int g_c1;

// 16B vectorized fp16 reduction: adds 8 halves (4x half2) atomically.
__device__ __forceinline__ void red_add_v4_f16x2(uint4* addr, uint4 v) {
    asm volatile("red.global.add.noftz.v4.f16x2 [%0], {%1, %2, %3, %4};"
                 :: "l"(addr), "r"(v.x), "r"(v.y), "r"(v.z), "r"(v.w)
                 : "memory");
}

__device__ __forceinline__ bool test_bit(const unsigned* fb, int n) {
    return (__ldg(fb + (n >> 5)) >> (n & 31)) & 1u;
}

__device__ __forceinline__ unsigned long long pack_edge(int row, int col, float v) {
    unsigned short vh = __half_as_ushort(__float2half(v));
    return (unsigned long long)(unsigned)row
         | ((unsigned long long)(unsigned)col << 18)
         | ((unsigned long long)vh << 36);
}

// ---- K_init: zero h1h + bitmasks + counters, and build fp16 emb table ----
#define H1H_WORDS (NUM_NODES * 8)                     // 1.6M uint4
#define CVT_GROUPS (NUM_NODES * EMB_DIM / 8)          // 1.6M (8 floats per thread)
#define CVT_USER_GROUPS (NUM_USERS * EMB_DIM / 8)     // 800K
#define INIT_TOTAL (H1H_WORDS + 2 * FB_U4 + CVT_GROUPS)
__global__ void k_init(const float4* __restrict__ user_emb,
                       const float4* __restrict__ item_emb) {
    int i = blockIdx.x * blockDim.x + threadIdx.x;
    if (i == 0) { g_c1 = 0; g_c2 = 0; }
    if (i < H1H_WORDS) {
        g_h1h[i] = make_uint4(0u, 0u, 0u, 0u);
    } else if (i < H1H_WORDS + FB_U4) {
        ((uint4*)g_fbA)[i - H1H_WORDS] = make_uint4(0u, 0u, 0u, 0u);
    } else if (i < H1H_WORDS + 2 * FB_U4) {
        ((uint4*)g_fbB)[i - H1H_WORDS - FB_U4] = make_uint4(0u, 0u, 0u, 0u);
    } else if (i < INIT_TOTAL) {
        int g = i - (H1H_WORDS + 2 * FB_U4);
        const float4* src = (g < CVT_USER_GROUPS)
            ? (user_emb + (size_t)g * 2)
            : (item_emb + (size_t)(g - CVT_USER_GROUPS) * 2);
        float4 a = __ldg(src);
        float4 b = __ldg(src + 1);
        __half2 h0 = __floats2half2_rn(a.x, a.y);
        __half2 h1 = __floats2half2_rn(a.z, a.w);
        __half2 h2 = __floats2half2_rn(b.x, b.y);
        __half2 h3 = __floats2half2_rn(b.z, b.w);
        uint4 o;
        o.x = *reinterpret_cast<unsigned*>(&h0);
        o.y = *reinterpret_cast<unsigned*>(&h1);
        o.z = *reinterpret_cast<unsigned*>(&h2);
        o.w = *reinterpret_cast<unsigned*>(&h3);
        g_embh[g] = o;
    }
}

// ---- K_flag: set batch bits (both masks) + zero those h2 rows (fp16) ----
__global__ void k_flag(const int* __restrict__ user,
                       const int* __restrict__ pos,
                       const int* __restrict__ neg) {
    int t = blockIdx.x * blockDim.x + threadIdx.x;   // 3*BATCH*16 threads
    int g = t >> 4;
    int c = t & 15;
    if (g >= 3 * BATCH) return;
    int node;
    if (g < BATCH)            node = user[g];
    else if (g < 2 * BATCH)   node = NUM_USERS + pos[g - BATCH];
    else                      node = NUM_USERS + neg[g - 2 * BATCH];
    if (c == 0) {
        unsigned bit = 1u << (node & 31);
        atomicOr(&g_fbA[node >> 5], bit);
        atomicOr(&g_fbB[node >> 5], bit);
    }
    if (c < 8)
        g_h2h[node * 8 + c] = make_uint4(0u, 0u, 0u, 0u);
}

// ---- K_compactA: layer-2 compaction (keep ~6%), 8B records + fbB[col] marking ----
#define COMPACT_THREADS (NUM_EDGES / 4)               // 1,000,000
__global__ void k_compactA(const int* __restrict__ edge_row,
                           const int* __restrict__ edge_col,
                           const float* __restrict__ edge_val) {
    __shared__ int s_cnt;
    __shared__ int s_base;
    __shared__ int s_warp_off[8];

    const int4*   rows4 = (const int4*)edge_row;
    const int4*   cols4 = (const int4*)edge_col;
    const float4* vals4 = (const float4*)edge_val;

    int t = blockIdx.x * blockDim.x + threadIdx.x;
    int lane = threadIdx.x & 31;
    int warp = threadIdx.x >> 5;
    if (threadIdx.x == 0) s_cnt = 0;
    __syncthreads();

    int4 r = make_int4(0, 0, 0, 0), cc = make_int4(0, 0, 0, 0);
    float4 vv = make_float4(0.f, 0.f, 0.f, 0.f);
    bool k0 = false, k1 = false, k2 = false, k3 = false;
    if (t < COMPACT_THREADS) {
        r  = __ldg(rows4 + t);
        k0 = test_bit(g_fbA, r.x);
        k1 = test_bit(g_fbA, r.y);
        k2 = test_bit(g_fbA, r.z);
        k3 = test_bit(g_fbA, r.w);
        if (k0 | k1 | k2 | k3) {
            cc = __ldg(cols4 + t);
            vv = __ldg(vals4 + t);
            if (k0) atomicOr(&g_fbB[cc.x >> 5], 1u << (cc.x & 31));
            if (k1) atomicOr(&g_fbB[cc.y >> 5], 1u << (cc.y & 31));
            if (k2) atomicOr(&g_fbB[cc.z >> 5], 1u << (cc.z & 31));
            if (k3) atomicOr(&g_fbB[cc.w >> 5], 1u << (cc.w & 31));
        }
    }
    int n = (int)k0 + (int)k1 + (int)k2 + (int)k3;
    int pre = n;
    #pragma unroll
    for (int o = 1; o < 32; o <<= 1) {
        int x = __shfl_up_sync(0xFFFFFFFFu, pre, o);
        if (lane >= o) pre += x;
    }
    int excl = pre - n;
    int wtot = __shfl_sync(0xFFFFFFFFu, pre, 31);

    if (lane == 31) s_warp_off[warp] = atomicAdd(&s_cnt, wtot);
    __syncthreads();
    if (threadIdx.x == 0) s_base = atomicAdd(&g_c2, s_cnt);
    __syncthreads();

    int p = s_base + s_warp_off[warp] + excl;
    if (k0) g_p2[p++] = pack_edge(r.x, cc.x, vv.x);
    if (k1) g_p2[p++] = pack_edge(r.y, cc.y, vv.y);
    if (k2) g_p2[p++] = pack_edge(r.z, cc.z, vv.z);
    if (k3) g_p2[p++] = pack_edge(r.w, cc.w, vv.w);
}

// ---- K_compactB: layer-1 compaction (keep ~70%), 8B packed records ----
__global__ void k_compactB(const int* __restrict__ edge_row,
                           const int* __restrict__ edge_col,
                           const float* __restrict__ edge_val) {
    __shared__ int s_cnt;
    __shared__ int s_base;
    __shared__ int s_warp_off[8];

    const int4*   rows4 = (const int4*)edge_row;
    const int4*   cols4 = (const int4*)edge_col;
    const float4* vals4 = (const float4*)edge_val;

    int t = blockIdx.x * blockDim.x + threadIdx.x;
    int lane = threadIdx.x & 31;
    int warp = threadIdx.x >> 5;
    if (threadIdx.x == 0) s_cnt = 0;
    __syncthreads();

    int4 r = make_int4(0, 0, 0, 0), cc = make_int4(0, 0, 0, 0);
    float4 vv = make_float4(0.f, 0.f, 0.f, 0.f);
    bool k0 = false, k1 = false, k2 = false, k3 = false;
    if (t < COMPACT_THREADS) {
        r  = __ldg(rows4 + t);
        cc = __ldg(cols4 + t);
        vv = __ldg(vals4 + t);
        k0 = test_bit(g_fbB, r.x);
        k1 = test_bit(g_fbB, r.y);
        k2 = test_bit(g_fbB, r.z);
        k3 = test_bit(g_fbB, r.w);
    }
    int n = (int)k0 + (int)k1 + (int)k2 + (int)k3;
    int pre = n;
    #pragma unroll
    for (int o = 1; o < 32; o <<= 1) {
        int x = __shfl_up_sync(0xFFFFFFFFu, pre, o);
        if (lane >= o) pre += x;
    }
    int excl = pre - n;
    int wtot = __shfl_sync(0xFFFFFFFFu, pre, 31);

    if (lane == 31) s_warp_off[warp] = atomicAdd(&s_cnt, wtot);
    __syncthreads();
    if (threadIdx.x == 0) s_base = atomicAdd(&g_c1, s_cnt);
    __syncthreads();

    int p = s_base + s_warp_off[warp] + excl;
    if (k0) g_p1[p++] = pack_edge(r.x, cc.x, vv.x);
    if (k1) g_p1[p++] = pack_edge(r.y, cc.y, vv.y);
    if (k2) g_p1[p++] = pack_edge(r.z, cc.z, vv.z);
    if (k3) g_p1[p++] = pack_edge(r.w, cc.w, vv.w);
}

// ---- K1: SPMM layer 1 over packed list: h1h[row] += val * embh[col] ----
// 8 lanes/edge: lane loads 16B (8 fp16), scales, reds 16B fp16. ILP=4.
#define SPMM1_THREADS (8 * 1024 * 1024)   // * 4 slots = 32M max items (4M edges * 8)
__global__ void k_spmm1(void) {
    long long total = (long long)g_c1 * 8;
    long long t = (long long)blockIdx.x * blockDim.x + threadIdx.x;

    #pragma unroll
    for (int k = 0; k < 4; k++) {
        long long item = t + (long long)k * SPMM1_THREADS;
        if (item < total) {
            int idx = (int)(item >> 3);
            int c = (int)(item & 7);
            unsigned long long p = __ldg(&g_p1[idx]);   // broadcast across 8 lanes
            int row = (int)(p & 0x3FFFFull);
            int col = (int)((p >> 18) & 0x3FFFFull);
            __half vh = __ushort_as_half((unsigned short)(p >> 36));
            __half2 vh2 = __half2half2(vh);

            uint4 u = __ldg(&g_embh[((size_t)col << 3) + c]);
            __half2 a = *reinterpret_cast<__half2*>(&u.x);
            __half2 b = *reinterpret_cast<__half2*>(&u.y);
            __half2 d = *reinterpret_cast<__half2*>(&u.z);
            __half2 e = *reinterpret_cast<__half2*>(&u.w);
            a = __hmul2(a, vh2);
            b = __hmul2(b, vh2);
            d = __hmul2(d, vh2);
            e = __hmul2(e, vh2);
            uint4 o;
            o.x = *reinterpret_cast<unsigned*>(&a);
            o.y = *reinterpret_cast<unsigned*>(&b);
            o.z = *reinterpret_cast<unsigned*>(&d);
            o.w = *reinterpret_cast<unsigned*>(&e);
            red_add_v4_f16x2(&g_h1h[((size_t)row << 3) + c], o);
        }
    }
}

// ---- K2: SPMM layer 2: h2h[row] += val * h1h[col] (fp16 gather, fp16 red) ----
// 8 lanes/edge over packed recs; fp32 math, fp16 pack, 16B red.
__global__ void k_spmm2(void) {
    long long total = (long long)g_c2 * 8;
    long long stride = (long long)gridDim.x * blockDim.x;
    for (long long t = (long long)blockIdx.x * blockDim.x + threadIdx.x;
         t < total; t += stride) {
        int idx = (int)(t >> 3);
        int c = (int)(t & 7);
        unsigned long long p = __ldg(&g_p2[idx]);
        int row = (int)(p & 0x3FFFFull);
        int col = (int)((p >> 18) & 0x3FFFFull);
        float v = __half2float(__ushort_as_half((unsigned short)(p >> 36)));

        uint4 u = __ldg(&g_h1h[((size_t)col << 3) + c]);
        __half2 a = *reinterpret_cast<__half2*>(&u.x);
        __half2 b = *reinterpret_cast<__half2*>(&u.y);
        __half2 d = *reinterpret_cast<__half2*>(&u.z);
        __half2 e = *reinterpret_cast<__half2*>(&u.w);
        float2 fa = __half22float2(a);
        float2 fb = __half22float2(b);
        float2 fd = __half22float2(d);
        float2 fe = __half22float2(e);
        __half2 o0 = __floats2half2_rn(v * fa.x, v * fa.y);
        __half2 o1 = __floats2half2_rn(v * fb.x, v * fb.y);
        __half2 o2 = __floats2half2_rn(v * fd.x, v * fd.y);
        __half2 o3 = __floats2half2_rn(v * fe.x, v * fe.y);
        uint4 o;
        o.x = *reinterpret_cast<unsigned*>(&o0);
        o.y = *reinterpret_cast<unsigned*>(&o1);
        o.z = *reinterpret_cast<unsigned*>(&o2);
        o.w = *reinterpret_cast<unsigned*>(&o3);
        red_add_v4_f16x2(&g_h2h[((size_t)row << 3) + c], o);
    }
}

// ---- K3: gather acc at batch nodes, dot, write scores ----
__global__ void k_score(const int* __restrict__ user,
                        const int* __restrict__ pos,
                        const int* __restrict__ neg,
                        const float2* __restrict__ user_emb2,
                        const float2* __restrict__ item_emb2,
                        float* __restrict__ out) {
    int w = (blockIdx.x * blockDim.x + threadIdx.x) >> 5;
    int lane = threadIdx.x & 31;
    if (w >= BATCH) return;
    int nu = user[w];
    int np = NUM_USERS + pos[w];
    int nn = NUM_USERS + neg[w];

    const unsigned* h1u = (const unsigned*)g_h1h;   // 2 halves per word
    const unsigned* h2u = (const unsigned*)g_h2h;
    const int L = EMB_DIM / 2;

    unsigned w1u = __ldg(&h1u[(size_t)nu * L + lane]);
    unsigned w2u = __ldg(&h2u[(size_t)nu * L + lane]);
    float2 u1 = __half22float2(*reinterpret_cast<__half2*>(&w1u));
    float2 u2 = __half22float2(*reinterpret_cast<__half2*>(&w2u));
    float2 ue = user_emb2[(size_t)nu * L + lane];
    float ux = ue.x + u1.x + u2.x;
    float uy = ue.y + u1.y + u2.y;

    unsigned w1p = __ldg(&h1u[(size_t)np * L + lane]);
    unsigned w2p = __ldg(&h2u[(size_t)np * L + lane]);
    float2 p1 = __half22float2(*reinterpret_cast<__half2*>(&w1p));
    float2 p2 = __half22float2(*reinterpret_cast<__half2*>(&w2p));
    float2 pe = item_emb2[(size_t)(np - NUM_USERS) * L + lane];
    float px = pe.x + p1.x + p2.x;
    float py = pe.y + p1.y + p2.y;

    unsigned w1n = __ldg(&h1u[(size_t)nn * L + lane]);
    unsigned w2n = __ldg(&h2u[(size_t)nn * L + lane]);
    float2 n1 = __half22float2(*reinterpret_cast<__half2*>(&w1n));
    float2 n2 = __half22float2(*reinterpret_cast<__half2*>(&w2n));
    float2 ne = item_emb2[(size_t)(nn - NUM_USERS) * L + lane];
    float nx = ne.x + n1.x + n2.x;
    float ny = ne.y + n1.y + n2.y;

    float sp = ux * px + uy * py;
    float sn = ux * nx + uy * ny;
    #pragma unroll
    for (int off = 16; off > 0; off >>= 1) {
        sp += __shfl_xor_sync(0xFFFFFFFFu, sp, off);
        sn += __shfl_xor_sync(0xFFFFFFFFu, sn, off);
    }
    if (lane == 0) {
        const float inv9 = 1.0f / 9.0f;
        out[w]         = sp * inv9;
        out[BATCH + w] = sn * inv9;
    }
}

extern "C" void kernel_launch(void* const* d_in, const int* in_sizes, int n_in,
                              void* d_out, int out_size) {
    const int*   user     = (const int*)  d_in[0];
    const int*   pos      = (const int*)  d_in[1];
    const int*   neg      = (const int*)  d_in[2];
    const int*   edge_row = (const int*)  d_in[3];
    const int*   edge_col = (const int*)  d_in[4];
    const float* edge_val = (const float*)d_in[5];
    const float* user_emb = (const float*)d_in[6];
    const float* item_emb = (const float*)d_in[7];
    float* out = (float*)d_out;

    // Init: zero h1h/bitmasks/counters + build fp16 emb table
    k_init<<<(INIT_TOTAL + 255) / 256, 256>>>((const float4*)user_emb,
                                              (const float4*)item_emb);
    // Batch flag bits + zero needed h2 rows
    {
        int total = 3 * BATCH * CHUNKS;
        k_flag<<<(total + 255) / 256, 256>>>(user, pos, neg);
    }
    // Compact layer-2 edges (bitmask filter, ~6% keep) + mark fbB[col]
    k_compactA<<<(COMPACT_THREADS + 255) / 256, 256>>>(edge_row, edge_col, edge_val);
    // Compact layer-1 edges (bitmask filter, ~70% keep) into 8B packed records
    k_compactB<<<(COMPACT_THREADS + 255) / 256, 256>>>(edge_row, edge_col, edge_val);
    // SPMM layer 1 (fp16 gather + fp16 vector red, ILP=4)
    k_spmm1<<<SPMM1_THREADS / 256, 256>>>();
    // SPMM layer 2 (fp16 gather + fp16 vector red)
    k_spmm2<<<8192, 256>>>();
    // Scores
    {
        int threads = 256;
        int blocks = (BATCH * 32 + threads - 1) / threads;
        k_score<<<blocks, threads>>>(user, pos, neg,
                                     (const float2*)user_emb, (const float2*)item_emb,
                                     out);
    }
}